// round 2
// baseline (speedup 1.0000x reference)
#include <cuda_runtime.h>
#include <cstdint>

typedef unsigned long long ull;

#define BB       8
#define NPTS     8192
#define RM       8
#define NT       128
#define NTHREADS 128
#define MCHUNK   (NTHREADS * RM)   // 1024
#define MCHUNKS  (NPTS / MCHUNK)   // 8
#define NSPLIT   8
#define NCHUNK   (NPTS / NSPLIT)   // 1024

// ---- scratch (no allocations allowed) ----
__device__ float4   g_p4[BB * NPTS];      // (px,py,pz,|p|^2)
__device__ float4   g_t4[BB * NPTS];      // (tx,ty,tz,|t|^2)
__device__ unsigned g_rowmin[BB * NPTS];  // min over preds, per target  (uint-ordered nonneg float)
__device__ unsigned g_colmin[BB * NPTS];  // min over targets, per pred

// ---- f32x2 packed helpers (Blackwell packed fp32) ----
__device__ __forceinline__ ull splat2(float v) {
    ull r;
    asm("mov.b64 %0, {%1, %2};" : "=l"(r) : "f"(v), "f"(v));
    return r;
}
__device__ __forceinline__ void unpack2(ull v, float& lo, float& hi) {
    asm("mov.b64 {%0, %1}, %2;" : "=f"(lo), "=f"(hi) : "l"(v));
}
#define FMA2(d, a, b, c) asm("fma.rn.f32x2 %0, %1, %2, %3;" : "=l"(d) : "l"(a), "l"(b), "l"(c))
#define ADD2(d, a, b)    asm("add.rn.f32x2 %0, %1, %2;"     : "=l"(d) : "l"(a), "l"(b))

__device__ __forceinline__ unsigned redux_min_u32(unsigned v) {
    unsigned r;
    asm volatile("redux.sync.min.u32 %0, %1, 0xffffffff;" : "=r"(r) : "r"(v));
    return r;
}

// ---- pack inputs, compute squared norms, init mins ----
__global__ void prep_kernel(const float* __restrict__ pred, const float* __restrict__ targ) {
    int idx = blockIdx.x * blockDim.x + threadIdx.x;
    if (idx >= BB * NPTS) return;
    float px = pred[3 * idx + 0], py = pred[3 * idx + 1], pz = pred[3 * idx + 2];
    g_p4[idx] = make_float4(px, py, pz, px * px + py * py + pz * pz);
    float tx = targ[3 * idx + 0], ty = targ[3 * idx + 1], tz = targ[3 * idx + 2];
    g_t4[idx] = make_float4(tx, ty, tz, tx * tx + ty * ty + tz * tz);
    g_rowmin[idx] = 0x7F800000u;  // +inf
    g_colmin[idx] = 0x7F800000u;
}

// ---- fused distance + dual-min kernel (broadcast scheme) ----
// Block: 128 threads. Thread owns RM=8 target rows (m = mc*1024 + k*128 + tid),
// with splat-packed constants in registers. Pred tile (128 preds) in smem in
// pair-split layout: slot [2i],[2i+1] hold components of preds (i, i+64).
// Per j, ALL lanes read the SAME pred pair (broadcast LDS, immediate offsets),
// compute 16 distances (8 targets x 2 preds), update register row-mins, and
// reduce the warp's col-min contribution with redux.sync (lane 0 -> global RED).
__global__ void __launch_bounds__(NTHREADS) chamfer_main() {
    const int b = blockIdx.z, mc = blockIdx.y, ns = blockIdx.x;
    const int tid = threadIdx.x, lane = tid & 31;

    const float4* __restrict__ P = g_p4 + b * NPTS + ns * NCHUNK;
    const float4* __restrict__ T = g_t4 + b * NPTS + mc * MCHUNK;

    // target constants: dist = (p2 + t2) + (-2tx)*px + (-2ty)*py + (-2tz)*pz
    ull axp[RM], ayp[RM], azp[RM], t2p[RM];
#pragma unroll
    for (int k = 0; k < RM; k++) {
        float4 t = T[k * NTHREADS + tid];
        axp[k] = splat2(-2.0f * t.x);
        ayp[k] = splat2(-2.0f * t.y);
        azp[k] = splat2(-2.0f * t.z);
        t2p[k] = splat2(t.w);
    }
    float rlo[RM], rhi[RM];
#pragma unroll
    for (int k = 0; k < RM; k++) { rlo[k] = INFINITY; rhi[k] = INFINITY; }

    __shared__ __align__(16) float s_px[NT], s_py[NT], s_pz[NT], s_pw[NT];

    unsigned* __restrict__ colmin = g_colmin + b * NPTS + ns * NCHUNK;

    for (int t0 = 0; t0 < NCHUNK; t0 += NT) {
        __syncthreads();
        {
            float4 p = P[t0 + tid];
            int i = tid & 63, h = tid >> 6;
            s_px[2 * i + h] = p.x;
            s_py[2 * i + h] = p.y;
            s_pz[2 * i + h] = p.z;
            s_pw[2 * i + h] = p.w;
        }
        __syncthreads();

#pragma unroll 8
        for (int j = 0; j < 64; j++) {
            // broadcast loads, immediate offsets (same address for all lanes)
            ull pxp = *(const ull*)&s_px[2 * j];
            ull pyp = *(const ull*)&s_py[2 * j];
            ull pzp = *(const ull*)&s_pz[2 * j];
            ull pwp = *(const ull*)&s_pw[2 * j];
            float clo = INFINITY, chi = INFINITY;
#pragma unroll
            for (int k = 0; k < RM; k++) {
                ull acc;
                ADD2(acc, pwp, t2p[k]);
                FMA2(acc, azp[k], pzp, acc);
                FMA2(acc, ayp[k], pyp, acc);
                FMA2(acc, axp[k], pxp, acc);
                float dlo, dhi;
                unpack2(acc, dlo, dhi);
                rlo[k] = fminf(rlo[k], dlo);
                rhi[k] = fminf(rhi[k], dhi);
                clo = fminf(clo, dlo);
                chi = fminf(chi, dhi);
            }
            // warp col-min for preds (t0+j, t0+j+64); clamp >=0 keeps uint ordering exact
            unsigned wlo = redux_min_u32(__float_as_uint(fmaxf(clo, 0.0f)));
            unsigned whi = redux_min_u32(__float_as_uint(fmaxf(chi, 0.0f)));
            if (lane == 0) {
                atomicMin(&colmin[t0 + j], wlo);
                atomicMin(&colmin[t0 + j + 64], whi);
            }
        }
    }

#pragma unroll
    for (int k = 0; k < RM; k++) {
        float v = fmaxf(fminf(rlo[k], rhi[k]), 0.0f);
        atomicMin(&g_rowmin[b * NPTS + mc * MCHUNK + k * NTHREADS + tid], __float_as_uint(v));
    }
}

// ---- final reduction: loss = mean(rowmin) + mean(colmin), both over B*NPTS ----
__global__ void reduce_kernel(float* __restrict__ out) {
    __shared__ float sh[32];
    int tid = threadIdx.x;
    float s = 0.f;
    for (int i = tid; i < BB * NPTS; i += 1024)
        s += __uint_as_float(g_rowmin[i]) + __uint_as_float(g_colmin[i]);
#pragma unroll
    for (int o = 16; o; o >>= 1) s += __shfl_down_sync(0xFFFFFFFFu, s, o);
    if ((tid & 31) == 0) sh[tid >> 5] = s;
    __syncthreads();
    if (tid < 32) {
        float v = sh[tid];
#pragma unroll
        for (int o = 16; o; o >>= 1) v += __shfl_down_sync(0xFFFFFFFFu, v, o);
        if (tid == 0) out[0] = v / (float)(BB * NPTS);
    }
}

extern "C" void kernel_launch(void* const* d_in, const int* in_sizes, int n_in,
                              void* d_out, int out_size) {
    const float* pred = (const float*)d_in[0];
    const float* targ = (const float*)d_in[1];
    prep_kernel<<<(BB * NPTS + 255) / 256, 256>>>(pred, targ);
    chamfer_main<<<dim3(NSPLIT, MCHUNKS, BB), NTHREADS>>>();
    reduce_kernel<<<1, 1024>>>((float*)d_out);
}

// round 6
// speedup vs baseline: 1.1486x; 1.1486x over previous
#include <cuda_runtime.h>
#include <cstdint>

typedef unsigned long long ull;

#define BB       8
#define NPTS     8192
#define RM       8
#define NT       128
#define NTHREADS 128
#define MCHUNK   (NTHREADS * RM)   // 1024
#define MCHUNKS  (NPTS / MCHUNK)   // 8
#define NSPLIT   16
#define NCHUNK   (NPTS / NSPLIT)   // 512

// ---- scratch (no allocations allowed) ----
__device__ float4   g_p4[BB * NPTS];      // (px,py,pz,|p|^2)
__device__ float4   g_t4[BB * NPTS];      // (tx,ty,tz,|t|^2)
__device__ unsigned g_rowmin[BB * NPTS];  // min over preds, per target (uint-ordered nonneg float)
__device__ unsigned g_colmin[BB * NPTS];  // min over targets, per pred

// ---- packed f32x2 helpers (sm_100a packed fp32: add/mul/fma ONLY — no min) ----
__device__ __forceinline__ ull splat2(float v) {
    ull r;
    asm("mov.b64 %0, {%1, %2};" : "=l"(r) : "f"(v), "f"(v));
    return r;
}
__device__ __forceinline__ void unpack2(ull v, float& lo, float& hi) {
    asm("mov.b64 {%0, %1}, %2;" : "=f"(lo), "=f"(hi) : "l"(v));
}
#define FMA2(d, a, b, c) asm("fma.rn.f32x2 %0, %1, %2, %3;" : "=l"(d) : "l"(a), "l"(b), "l"(c))
#define ADD2(d, a, b)    asm("add.rn.f32x2 %0, %1, %2;"     : "=l"(d) : "l"(a), "l"(b))

__device__ __forceinline__ unsigned redux_min_u32(unsigned v) {
    unsigned r;
    asm volatile("redux.sync.min.u32 %0, %1, 0xffffffff;" : "=r"(r) : "r"(v));
    return r;
}

// ---- pack inputs, compute squared norms, init mins ----
__global__ void prep_kernel(const float* __restrict__ pred, const float* __restrict__ targ) {
    int idx = blockIdx.x * blockDim.x + threadIdx.x;
    if (idx >= BB * NPTS) return;
    float px = pred[3 * idx + 0], py = pred[3 * idx + 1], pz = pred[3 * idx + 2];
    g_p4[idx] = make_float4(px, py, pz, px * px + py * py + pz * pz);
    float tx = targ[3 * idx + 0], ty = targ[3 * idx + 1], tz = targ[3 * idx + 2];
    g_t4[idx] = make_float4(tx, ty, tz, tx * tx + ty * ty + tz * tz);
    g_rowmin[idx] = 0x7F800000u;  // +inf
    g_colmin[idx] = 0x7F800000u;
}

// ---- fused distance + dual-min kernel ----
// Thread owns RM=8 target rows (splat-packed constants in registers).
// Pred tile (128 preds) in smem, pair-split: slots [2i],[2i+1] = preds (i, i+64).
// Per j all lanes broadcast-read the same pred pair (immediate-offset LDS.64),
// compute 16 distances (8 targets x 2 preds) with fma.rn.f32x2. Row-mins stay
// in registers. Col-min candidates reduce over k via a 7+7 tree, then ACROSS
// LANES via redux.sync.min.u32 on clamped nonneg float bits (uint order ==
// float order for values >= 0); lane 0 pushes to global atomicMin.
__global__ void __launch_bounds__(NTHREADS) chamfer_main() {
    const int b = blockIdx.z, mc = blockIdx.y, ns = blockIdx.x;
    const int tid = threadIdx.x, lane = tid & 31;

    const float4* __restrict__ P = g_p4 + b * NPTS + ns * NCHUNK;
    const float4* __restrict__ T = g_t4 + b * NPTS + mc * MCHUNK;

    // dist = (p2 + t2) + (-2tx)*px + (-2ty)*py + (-2tz)*pz
    ull axp[RM], ayp[RM], azp[RM], t2p[RM];
#pragma unroll
    for (int k = 0; k < RM; k++) {
        float4 t = T[k * NTHREADS + tid];
        axp[k] = splat2(-2.0f * t.x);
        ayp[k] = splat2(-2.0f * t.y);
        azp[k] = splat2(-2.0f * t.z);
        t2p[k] = splat2(t.w);
    }
    float rlo[RM], rhi[RM];
#pragma unroll
    for (int k = 0; k < RM; k++) { rlo[k] = INFINITY; rhi[k] = INFINITY; }

    __shared__ __align__(16) float s_px[NT], s_py[NT], s_pz[NT], s_pw[NT];

    unsigned* __restrict__ colmin = g_colmin + b * NPTS + ns * NCHUNK;

    for (int t0 = 0; t0 < NCHUNK; t0 += NT) {
        __syncthreads();
        {
            float4 p = P[t0 + tid];
            int i = tid & 63, h = tid >> 6;
            s_px[2 * i + h] = p.x;
            s_py[2 * i + h] = p.y;
            s_pz[2 * i + h] = p.z;
            s_pw[2 * i + h] = p.w;
        }
        __syncthreads();

#pragma unroll 8
        for (int j = 0; j < 64; j++) {
            // broadcast loads, immediate offsets (conflict-free LDS.64)
            ull pxp = *(const ull*)&s_px[2 * j];
            ull pyp = *(const ull*)&s_py[2 * j];
            ull pzp = *(const ull*)&s_pz[2 * j];
            ull pwp = *(const ull*)&s_pw[2 * j];
            float dlo[RM], dhi[RM];
#pragma unroll
            for (int k = 0; k < RM; k++) {
                ull acc;
                ADD2(acc, pwp, t2p[k]);
                FMA2(acc, azp[k], pzp, acc);
                FMA2(acc, ayp[k], pyp, acc);
                FMA2(acc, axp[k], pxp, acc);
                unpack2(acc, dlo[k], dhi[k]);
                rlo[k] = fminf(rlo[k], dlo[k]);
                rhi[k] = fminf(rhi[k], dhi[k]);
            }
            // col-min trees over k (7 + 7 FMNMX)
            float clo = fminf(fminf(fminf(dlo[0], dlo[1]), fminf(dlo[2], dlo[3])),
                              fminf(fminf(dlo[4], dlo[5]), fminf(dlo[6], dlo[7])));
            float chi = fminf(fminf(fminf(dhi[0], dhi[1]), fminf(dhi[2], dhi[3])),
                              fminf(fminf(dhi[4], dhi[5]), fminf(dhi[6], dhi[7])));
            // cross-lane min (clamp >=0 keeps uint ordering exact), lane0 -> global
            unsigned wlo = redux_min_u32(__float_as_uint(fmaxf(clo, 0.0f)));
            unsigned whi = redux_min_u32(__float_as_uint(fmaxf(chi, 0.0f)));
            if (lane == 0) {
                atomicMin(&colmin[t0 + j], wlo);
                atomicMin(&colmin[t0 + j + 64], whi);
            }
        }
    }

#pragma unroll
    for (int k = 0; k < RM; k++) {
        float v = fmaxf(fminf(rlo[k], rhi[k]), 0.0f);
        atomicMin(&g_rowmin[b * NPTS + mc * MCHUNK + k * NTHREADS + tid], __float_as_uint(v));
    }
}

// ---- final reduction: loss = mean(rowmin) + mean(colmin) ----
__global__ void reduce_kernel(float* __restrict__ out) {
    __shared__ float sh[32];
    int tid = threadIdx.x;
    float s = 0.f;
    for (int i = tid; i < BB * NPTS; i += 1024)
        s += __uint_as_float(g_rowmin[i]) + __uint_as_float(g_colmin[i]);
#pragma unroll
    for (int o = 16; o; o >>= 1) s += __shfl_down_sync(0xFFFFFFFFu, s, o);
    if ((tid & 31) == 0) sh[tid >> 5] = s;
    __syncthreads();
    if (tid < 32) {
        float v = sh[tid];
#pragma unroll
        for (int o = 16; o; o >>= 1) v += __shfl_down_sync(0xFFFFFFFFu, v, o);
        if (tid == 0) out[0] = v / (float)(BB * NPTS);
    }
}

extern "C" void kernel_launch(void* const* d_in, const int* in_sizes, int n_in,
                              void* d_out, int out_size) {
    const float* pred = (const float*)d_in[0];
    const float* targ = (const float*)d_in[1];
    prep_kernel<<<(BB * NPTS + 255) / 256, 256>>>(pred, targ);
    chamfer_main<<<dim3(NSPLIT, MCHUNKS, BB), NTHREADS>>>();
    reduce_kernel<<<1, 1024>>>((float*)d_out);
}